// round 2
// baseline (speedup 1.0000x reference)
#include <cuda_runtime.h>
#include <cuda_bf16.h>
#include <cstdint>

// EdgeConvE: out[v,h] = sum_w A[v,w] * relu(S[v,h] + T[w,h] + sum_e E[v,w,e]*We[e,h])
// N=1024, F=32, E_ATTR=8, H=64.
// R2 strategy: edge term via mma.sync tf32 (m16n8k8), T passed as the MMA C operand,
// f32x2 epilogue with zero-MOV packing; one warp per v (1024 one-warp CTAs).

#define N_NODES 1024
#define F_NODE  32
#define E_ATTR  8
#define H_OUT   64

typedef unsigned long long u64;

// ---------- f32x2 helpers ----------
__device__ __forceinline__ u64 pk(float lo, float hi) {
    u64 r; asm("mov.b64 %0, {%1,%2};" : "=l"(r) : "f"(lo), "f"(hi)); return r;
}
__device__ __forceinline__ u64 pk1(float x) {
    u64 r; asm("mov.b64 %0, {%1,%1};" : "=l"(r) : "f"(x)); return r;
}
__device__ __forceinline__ void upk(u64 p, float& lo, float& hi) {
    asm("mov.b64 {%0,%1}, %2;" : "=f"(lo), "=f"(hi) : "l"(p));
}
__device__ __forceinline__ u64 fma2(u64 a, u64 b, u64 c) {
    u64 d; asm("fma.rn.f32x2 %0, %1, %2, %3;" : "=l"(d) : "l"(a), "l"(b), "l"(c)); return d;
}
__device__ __forceinline__ u64 add2(u64 a, u64 b) {
    u64 d; asm("add.rn.f32x2 %0, %1, %2;" : "=l"(d) : "l"(a), "l"(b)); return d;
}
__device__ __forceinline__ uint32_t to_tf32(float f) {
    uint32_t u; asm("cvt.rna.tf32.f32 %0, %1;" : "=r"(u) : "f"(f)); return u;
}

// ---------- scratch ----------
__device__ float g_S[N_NODES * H_OUT];   // S[v,h] = X@(Ws-Wd) + b   (256 KB)
__device__ float g_T[N_NODES * H_OUT];   // T[w,h] = X@Wd            (256 KB)

// ---------- kernel 1: S and T (smem-cached W) ----------
// grid 256, block 256: 4 v per block, thread = (vl, h)
__global__ void prep_st(const float* __restrict__ X, const float* __restrict__ W,
                        const float* __restrict__ b) {
    __shared__ float ws[2 * F_NODE * H_OUT];   // 16 KB: rows 0..63 of W
    __shared__ float xs[4][F_NODE];
    const int tid = threadIdx.x;
    const int v0 = blockIdx.x * 4;
    for (int i = tid; i < 2 * F_NODE * H_OUT; i += 256) ws[i] = W[i];
    if (tid < 4 * F_NODE) xs[tid >> 5][tid & 31] = X[v0 * F_NODE + tid];
    __syncthreads();
    const int h = tid & 63;
    const int vl = tid >> 6;
    float s = b[h], t = 0.0f;
#pragma unroll
    for (int f = 0; f < F_NODE; f++) {
        float x  = xs[vl][f];
        float wv = ws[f * H_OUT + h];
        float wd = ws[(f + F_NODE) * H_OUT + h];
        s = fmaf(x, wv - wd, s);
        t = fmaf(x, wd, t);
    }
    g_S[(v0 + vl) * H_OUT + h] = s;
    g_T[(v0 + vl) * H_OUT + h] = t;
}

// ---------- kernel 2: main (one warp per v) ----------
// mma.sync m16n8k8 tf32: M = 16 w-rows, N = 8 h-cols, K = 8 edge attrs.
// C-in = T[w,h] frag (frag-shaped!), epilogue adds S, relu, A-weighted accumulate.
__global__ void __launch_bounds__(32)
edge_main(const float* __restrict__ E, const int* __restrict__ A,
          const float* __restrict__ W, float* __restrict__ out) {
    const int v    = blockIdx.x;
    const int lane = threadIdx.x;
    const int gid  = lane >> 2;    // 0..7  (row group)
    const int tid4 = lane & 3;     // 0..3  (thread in group)

    // B frags: We[e,h] in tf32, 8 n-tiles, loop-invariant
    uint32_t bf0[8], bf1[8];
#pragma unroll
    for (int j = 0; j < 8; j++) {
        bf0[j] = to_tf32(W[(2 * F_NODE + tid4)     * H_OUT + j * 8 + gid]);
        bf1[j] = to_tf32(W[(2 * F_NODE + tid4 + 4) * H_OUT + j * 8 + gid]);
    }
    // S pairs (adjacent h -> free u64 pack via float2 load)
    u64 S2[8];
#pragma unroll
    for (int j = 0; j < 8; j++) {
        float2 s = *(const float2*)&g_S[v * H_OUT + j * 8 + 2 * tid4];
        S2[j] = pk(s.x, s.y);
    }
    u64 acc[8];
#pragma unroll
    for (int j = 0; j < 8; j++) acc[j] = pk(0.0f, 0.0f);

    const float* __restrict__ Ev = E + (size_t)v * (N_NODES * E_ATTR);
    const int*   __restrict__ Av = A + v * N_NODES;

#pragma unroll 2
    for (int wt = 0; wt < N_NODES / 16; wt++) {
        const int r0 = wt * 16 + gid;
        const int r1 = r0 + 8;
        // E frag (tf32): a0:(r0,t) a1:(r1,t) a2:(r0,t+4) a3:(r1,t+4)
        uint32_t a0 = to_tf32(Ev[r0 * E_ATTR + tid4]);
        uint32_t a1 = to_tf32(Ev[r1 * E_ATTR + tid4]);
        uint32_t a2 = to_tf32(Ev[r0 * E_ATTR + tid4 + 4]);
        uint32_t a3 = to_tf32(Ev[r1 * E_ATTR + tid4 + 4]);
        // adjacency for this lane's two w rows
        u64 ap0 = pk1((float)Av[r0]);
        u64 ap1 = pk1((float)Av[r1]);
#pragma unroll
        for (int j = 0; j < 8; j++) {
            // C-in = T[w,h] (exactly frag-shaped)
            float2 ct0 = *(const float2*)&g_T[r0 * H_OUT + j * 8 + 2 * tid4];
            float2 ct1 = *(const float2*)&g_T[r1 * H_OUT + j * 8 + 2 * tid4];
            float d0, d1, d2, d3;
            asm("mma.sync.aligned.m16n8k8.row.col.f32.tf32.tf32.f32 "
                "{%0,%1,%2,%3}, {%4,%5,%6,%7}, {%8,%9}, {%10,%11,%12,%13};"
                : "=f"(d0), "=f"(d1), "=f"(d2), "=f"(d3)
                : "r"(a0), "r"(a1), "r"(a2), "r"(a3),
                  "r"(bf0[j]), "r"(bf1[j]),
                  "f"(ct0.x), "f"(ct0.y), "f"(ct1.x), "f"(ct1.y));
            // m = (edge + T) + S ; relu ; acc += a * relu(m)
            u64 m0 = add2(pk(d0, d1), S2[j]);
            u64 m1 = add2(pk(d2, d3), S2[j]);
            float r00, r01, r10, r11;
            upk(m0, r00, r01);
            upk(m1, r10, r11);
            r00 = fmaxf(r00, 0.0f); r01 = fmaxf(r01, 0.0f);
            r10 = fmaxf(r10, 0.0f); r11 = fmaxf(r11, 0.0f);
            acc[j] = fma2(ap0, pk(r00, r01), acc[j]);
            acc[j] = fma2(ap1, pk(r10, r11), acc[j]);
        }
    }

    // reduce over the 8 row-groups (lanes sharing tid4)
#pragma unroll
    for (int j = 0; j < 8; j++) {
        u64 a = acc[j];
        a = add2(a, __shfl_xor_sync(0xffffffffu, a, 4));
        a = add2(a, __shfl_xor_sync(0xffffffffu, a, 8));
        a = add2(a, __shfl_xor_sync(0xffffffffu, a, 16));
        acc[j] = a;
    }
    if (gid == 0) {
#pragma unroll
        for (int j = 0; j < 8; j++) {
            float lo, hi;
            upk(acc[j], lo, hi);
            *(float2*)&out[v * H_OUT + j * 8 + 2 * tid4] = make_float2(lo, hi);
        }
    }
}

// ---------- launch ----------
extern "C" void kernel_launch(void* const* d_in, const int* in_sizes, int n_in,
                              void* d_out, int out_size) {
    const int*   adj = (const int*)d_in[0];       // (1,1024,1024) int32
    const float* X   = (const float*)d_in[1];     // (1,1024,32)
    const float* E   = (const float*)d_in[2];     // (1,1024,1024,8)
    const float* W   = (const float*)d_in[3];     // (72,64)
    const float* b   = (const float*)d_in[4];     // (64,)
    float* out = (float*)d_out;                   // (1,1024,64)

    prep_st<<<N_NODES / 4, 256>>>(X, W, b);
    edge_main<<<N_NODES, 32>>>(E, adj, W, out);
}

// round 3
// speedup vs baseline: 2.0337x; 2.0337x over previous
#include <cuda_runtime.h>
#include <cuda_bf16.h>
#include <cstdint>

// EdgeConvE: out[v,h] = sum_w A[v,w] * relu(S[v,h] + T[w,h] + sum_e E[v,w,e]*We[e,h])
// N=1024, F=32, E_ATTR=8, H=64.
// R3: tf32 mma.sync m16n8k8 for edge term; T pre-fragmented into MMA-C layout
// (one coalesced LDG.128 per (wtile,j)); 8 v per block x 2 w-halves for T reuse
// in L1; scalar epilogue; deterministic two-half combine (no atomics).

#define N_NODES 1024
#define F_NODE  32
#define E_ATTR  8
#define H_OUT   64

__device__ __forceinline__ uint32_t to_tf32(float f) {
    uint32_t u; asm("cvt.rna.tf32.f32 %0, %1;" : "=r"(u) : "f"(f)); return u;
}

// ---------- scratch ----------
__device__ float  g_S [N_NODES * H_OUT];                 // 256 KB: S[v,h]=X@(Ws-Wd)+b
__device__ float4 g_Tf[(N_NODES / 16) * 8 * 32];         // 256 KB: T in MMA-C frag layout
__device__ float  g_part[2][N_NODES * H_OUT];            // 512 KB: per-half partials

// ---------- kernel 1: S, fragged T ----------
// grid 256, block 256: 4 v per block, thread = (vl, h)
__global__ void prep_st(const float* __restrict__ X, const float* __restrict__ W,
                        const float* __restrict__ b) {
    __shared__ float ws[2 * F_NODE * H_OUT];   // 16 KB
    __shared__ float xs[4][F_NODE];
    const int tid = threadIdx.x;
    const int v0 = blockIdx.x * 4;
    for (int i = tid; i < 2 * F_NODE * H_OUT; i += 256) ws[i] = W[i];
    if (tid < 4 * F_NODE) xs[tid >> 5][tid & 31] = X[v0 * F_NODE + tid];
    __syncthreads();
    const int h  = tid & 63;
    const int vl = tid >> 6;
    float s = b[h], t = 0.0f;
#pragma unroll
    for (int f = 0; f < F_NODE; f++) {
        float x  = xs[vl][f];
        float wv = ws[f * H_OUT + h];
        float wd = ws[(f + F_NODE) * H_OUT + h];
        s = fmaf(x, wv - wd, s);
        t = fmaf(x, wd, t);
    }
    const int v = v0 + vl;
    g_S[v * H_OUT + h] = s;
    // scatter T into frag layout:
    // frag float4 for (wt, j, lane=gid*4+t4) = {T[r0][j*8+2t4], T[r0][j*8+2t4+1],
    //                                           T[r1][j*8+2t4], T[r1][j*8+2t4+1]}
    // r0 = wt*16+gid, r1 = r0+8.  Here w := v.
    const int wt   = v >> 4;
    const int gid  = v & 7;
    const int rs   = (v >> 3) & 1;        // 0 -> r0 slot, 1 -> r1 slot
    const int t4   = (h >> 1) & 3;
    const int j    = h >> 3;
    const int elem = (h & 1) + 2 * rs;
    reinterpret_cast<float*>(g_Tf)[(((wt * 8 + j) * 32) + gid * 4 + t4) * 4 + elem] = t;
}

// ---------- kernel 2: main ----------
// Block: 8 warps = 8 v's, all scanning the SAME w-half (T reuse via L1).
// Grid: (1024/8) * 2 halves = 256 blocks.
__global__ void __launch_bounds__(256, 2)
edge_main(const float* __restrict__ E, const int* __restrict__ A,
          const float* __restrict__ W) {
    const int vg   = blockIdx.x >> 1;
    const int half = blockIdx.x & 1;
    const int warp = threadIdx.x >> 5;
    const int lane = threadIdx.x & 31;
    const int gid  = lane >> 2;            // 0..7
    const int t4   = lane & 3;             // 0..3
    const int v    = vg * 8 + warp;

    // B frags (We in tf32), loop-invariant
    uint32_t bf0[8], bf1[8];
#pragma unroll
    for (int j = 0; j < 8; j++) {
        bf0[j] = to_tf32(W[(2 * F_NODE + t4)     * H_OUT + j * 8 + gid]);
        bf1[j] = to_tf32(W[(2 * F_NODE + t4 + 4) * H_OUT + j * 8 + gid]);
    }
    // S pairs for this lane's h columns
    float2 sj[8];
#pragma unroll
    for (int j = 0; j < 8; j++)
        sj[j] = *(const float2*)&g_S[v * H_OUT + j * 8 + 2 * t4];

    float acc0[8], acc1[8];
#pragma unroll
    for (int j = 0; j < 8; j++) { acc0[j] = 0.0f; acc1[j] = 0.0f; }

    const float* __restrict__ Ev = E + (size_t)v * (N_NODES * E_ATTR);
    const int*   __restrict__ Av = A + v * N_NODES;
    const float4* __restrict__ Tf = g_Tf;

    const int wt0 = half * 32;
#pragma unroll 2
    for (int wt = wt0; wt < wt0 + 32; wt++) {
        const int r0 = wt * 16 + gid;
        const int r1 = r0 + 8;
        // E frag (tf32)
        uint32_t a0 = to_tf32(Ev[r0 * E_ATTR + t4]);
        uint32_t a1 = to_tf32(Ev[r1 * E_ATTR + t4]);
        uint32_t a2 = to_tf32(Ev[r0 * E_ATTR + t4 + 4]);
        uint32_t a3 = to_tf32(Ev[r1 * E_ATTR + t4 + 4]);
        // adjacency (0/1) for this lane's two w rows
        float aF0 = (float)Av[r0];
        float aF1 = (float)Av[r1];
#pragma unroll
        for (int j = 0; j < 8; j++) {
            float4 c = Tf[(wt * 8 + j) * 32 + lane];   // coalesced 512B/warp
            float c0 = c.x + sj[j].x;
            float c1 = c.y + sj[j].y;
            float c2 = c.z + sj[j].x;
            float c3 = c.w + sj[j].y;
            float d0, d1, d2, d3;
            asm("mma.sync.aligned.m16n8k8.row.col.f32.tf32.tf32.f32 "
                "{%0,%1,%2,%3}, {%4,%5,%6,%7}, {%8,%9}, {%10,%11,%12,%13};"
                : "=f"(d0), "=f"(d1), "=f"(d2), "=f"(d3)
                : "r"(a0), "r"(a1), "r"(a2), "r"(a3),
                  "r"(bf0[j]), "r"(bf1[j]),
                  "f"(c0), "f"(c1), "f"(c2), "f"(c3));
            d0 = fmaxf(d0, 0.0f);
            d1 = fmaxf(d1, 0.0f);
            d2 = fmaxf(d2, 0.0f);
            d3 = fmaxf(d3, 0.0f);
            acc0[j] = fmaf(aF0, d0, acc0[j]);
            acc0[j] = fmaf(aF1, d2, acc0[j]);
            acc1[j] = fmaf(aF0, d1, acc1[j]);
            acc1[j] = fmaf(aF1, d3, acc1[j]);
        }
    }

    // reduce across the 8 row-groups (xor over gid bits: lanes 4,8,16)
#pragma unroll
    for (int j = 0; j < 8; j++) {
        float a = acc0[j], bq = acc1[j];
        a  += __shfl_xor_sync(0xffffffffu, a, 4);
        bq += __shfl_xor_sync(0xffffffffu, bq, 4);
        a  += __shfl_xor_sync(0xffffffffu, a, 8);
        bq += __shfl_xor_sync(0xffffffffu, bq, 8);
        a  += __shfl_xor_sync(0xffffffffu, a, 16);
        bq += __shfl_xor_sync(0xffffffffu, bq, 16);
        if (gid == 0)
            *(float2*)&g_part[half][v * H_OUT + j * 8 + 2 * t4] = make_float2(a, bq);
    }
}

// ---------- kernel 3: deterministic combine ----------
__global__ void combine(float* __restrict__ out) {
    const int i = blockIdx.x * 256 + threadIdx.x;
    out[i] = g_part[0][i] + g_part[1][i];
}

// ---------- launch ----------
extern "C" void kernel_launch(void* const* d_in, const int* in_sizes, int n_in,
                              void* d_out, int out_size) {
    const int*   adj = (const int*)d_in[0];       // (1,1024,1024) int32
    const float* X   = (const float*)d_in[1];     // (1,1024,32)
    const float* E   = (const float*)d_in[2];     // (1,1024,1024,8)
    const float* W   = (const float*)d_in[3];     // (72,64)
    const float* b   = (const float*)d_in[4];     // (64,)
    float* out = (float*)d_out;                   // (1,1024,64)

    prep_st<<<N_NODES / 4, 256>>>(X, W, b);
    edge_main<<<(N_NODES / 8) * 2, 256>>>(E, adj, W);
    combine<<<(N_NODES * H_OUT) / 256, 256>>>(out);
}